// round 11
// baseline (speedup 1.0000x reference)
#include <cuda_runtime.h>
#include <cuda_bf16.h>
#include <string.h>

#define T_STEPS 8192
#define HID     1024
#define G4      4096   // 4*HID
#define INW     1024
#define NCTA    128

// ---------------- static device scratch (no runtime allocation) --------------
__device__ float g_pre[(size_t)T_STEPS * G4];    // 128 MB: x-projection of gates
__device__ float g_hall[(size_t)T_STEPS * HID];  // 32 MB: all hidden states
// tagged h ring: element = (tag:32 << 32) | float_bits(h).  slot = t&1, tag = t+1
__device__ __align__(32) unsigned long long g_htag[2][HID];

// ---------------- small PTX helpers ------------------------------------------
__device__ __forceinline__ ulonglong2 ld_tag_v2(const unsigned long long* p) {
    ulonglong2 v;
    asm volatile("ld.relaxed.gpu.global.v2.u64 {%0,%1}, [%2];"
                 : "=l"(v.x), "=l"(v.y) : "l"(p) : "memory");
    return v;
}
__device__ __forceinline__ void st_tag_u64(unsigned long long* p, unsigned long long v) {
    asm volatile("st.relaxed.gpu.global.u64 [%0], %1;" :: "l"(p), "l"(v) : "memory");
}
__device__ __forceinline__ float2 ffma2(float2 a, float2 b, float2 c) {
    unsigned long long A, B, C, D;
    memcpy(&A, &a, 8); memcpy(&B, &b, 8); memcpy(&C, &c, 8);
    asm("fma.rn.f32x2 %0, %1, %2, %3;" : "=l"(D) : "l"(A), "l"(B), "l"(C));
    float2 d; memcpy(&d, &D, 8); return d;
}
__device__ __forceinline__ float2 fpack2(float a) {
    float2 r;
    unsigned long long R;
    asm("mov.b64 %0, {%1, %1};" : "=l"(R) : "f"(a));
    memcpy(&r, &R, 8); return r;
}
__device__ __forceinline__ float fsig(float x) {
    return __fdividef(1.0f, 1.0f + __expf(-x));
}
__device__ __forceinline__ float ftanh_acc(float x) {
    float xc = fminf(fmaxf(x, -15.0f), 15.0f);
    float e  = __expf(2.0f * xc);
    return __fdividef(e - 1.0f, e + 1.0f);
}
__device__ __forceinline__ void bar_pair(int id) {
    asm volatile("bar.sync %0, 64;" :: "r"(id) : "memory");
}

// ---------------- init: zero the tagged ring ----------------------------------
__global__ void init_tags_kernel() {
    int i = blockIdx.x * blockDim.x + threadIdx.x;
    if (i < 2 * HID) ((unsigned long long*)g_htag)[i] = 0ull;
}

// ---------------- fp32 NT GEMM: C = A*B^T + bias (reg-staged pipeline) --------
// A: [M x K] row-major (lda), B: [N x K] row-major (ldb), C: [M x N] (ldc)
// BM=BN=128, BK=16, 256 threads, 8x8 microtile (as 8x4 float2).
__device__ __forceinline__ void gemm_body(
    const float* __restrict__ A, int lda,
    const float* __restrict__ B, int ldb,
    const float* __restrict__ bias,
    float* __restrict__ C, int ldc, int K)
{
    __shared__ float As[16][132];
    __shared__ float Bs[16][132];

    const int tid  = threadIdx.x;
    const int tx   = tid & 15;          // N-dir microtile
    const int ty   = tid >> 4;          // M-dir microtile
    const int brow = blockIdx.y * 128;
    const int bcol = blockIdx.x * 128;
    const int lr   = tid >> 2;          // 0..63 (load row)
    const int lc   = (tid & 3) << 2;    // 0,4,8,12 (load col group)

    float2 acc[8][4];
#pragma unroll
    for (int i = 0; i < 8; i++)
#pragma unroll
        for (int j = 0; j < 4; j++) acc[i][j] = make_float2(0.0f, 0.0f);

    const float* Aptr = A + (size_t)(brow + lr) * lda + lc;
    const float* Bptr = B + (size_t)(bcol + lr) * ldb + lc;

    float4 va[2], vb[2];
#pragma unroll
    for (int r = 0; r < 2; r++) {
        va[r] = *(const float4*)(Aptr + (size_t)(64 * r) * lda);
        vb[r] = *(const float4*)(Bptr + (size_t)(64 * r) * ldb);
    }

    const int NT = K / 16;
    for (int tile = 0; tile < NT; ++tile) {
#pragma unroll
        for (int r = 0; r < 2; r++) {
            As[lc + 0][lr + 64 * r] = va[r].x;
            As[lc + 1][lr + 64 * r] = va[r].y;
            As[lc + 2][lr + 64 * r] = va[r].z;
            As[lc + 3][lr + 64 * r] = va[r].w;
            Bs[lc + 0][lr + 64 * r] = vb[r].x;
            Bs[lc + 1][lr + 64 * r] = vb[r].y;
            Bs[lc + 2][lr + 64 * r] = vb[r].z;
            Bs[lc + 3][lr + 64 * r] = vb[r].w;
        }
        __syncthreads();

        if (tile + 1 < NT) {
            const int k0 = (tile + 1) * 16;
#pragma unroll
            for (int r = 0; r < 2; r++) {
                va[r] = *(const float4*)(Aptr + (size_t)(64 * r) * lda + k0);
                vb[r] = *(const float4*)(Bptr + (size_t)(64 * r) * ldb + k0);
            }
        }

#pragma unroll
        for (int kk = 0; kk < 16; kk++) {
            float  ra[8];
            float2 rb[4];
            *(float4*)(ra)     = *(const float4*)&As[kk][ty * 8];
            *(float4*)(ra + 4) = *(const float4*)&As[kk][ty * 8 + 4];
            *(float4*)(&rb[0]) = *(const float4*)&Bs[kk][tx * 8];
            *(float4*)(&rb[2]) = *(const float4*)&Bs[kk][tx * 8 + 4];
#pragma unroll
            for (int i = 0; i < 8; i++) {
                float2 a2 = fpack2(ra[i]);
#pragma unroll
                for (int j = 0; j < 4; j++)
                    acc[i][j] = ffma2(a2, rb[j], acc[i][j]);
            }
        }
        __syncthreads();
    }

    float2 bv[4];
    *(float4*)(&bv[0]) = *(const float4*)&bias[bcol + tx * 8];
    *(float4*)(&bv[2]) = *(const float4*)&bias[bcol + tx * 8 + 4];
#pragma unroll
    for (int i = 0; i < 8; i++) {
        float4 o0, o1;
        o0.x = acc[i][0].x + bv[0].x; o0.y = acc[i][0].y + bv[0].y;
        o0.z = acc[i][1].x + bv[1].x; o0.w = acc[i][1].y + bv[1].y;
        o1.x = acc[i][2].x + bv[2].x; o1.y = acc[i][2].y + bv[2].y;
        o1.z = acc[i][3].x + bv[3].x; o1.w = acc[i][3].y + bv[3].y;
        float* crow = C + (size_t)(brow + ty * 8 + i) * ldc + bcol + tx * 8;
        *(float4*)(crow)     = o0;
        *(float4*)(crow + 4) = o1;
    }
}

__global__ void __launch_bounds__(256, 2) gemm_pre_kernel(
    const float* __restrict__ x, const float* __restrict__ Ww,
    const float* __restrict__ Wb)
{
    gemm_body(x, INW, Ww, INW + HID, Wb, g_pre, G4, INW);
}

__global__ void __launch_bounds__(256, 2) gemm_out_kernel(
    const float* __restrict__ ow, const float* __restrict__ ob,
    float* __restrict__ out)
{
    gemm_body(g_hall, HID, ow, HID, ob, out, HID, HID);
}

// ---------------- persistent LSTM recurrence ----------------------------------
// 128 CTAs x 512 threads (16 warps). CTA owns units [8b, 8b+8).
// Warp w (w<8):  rows rA=u (i-gate),      rB=u+1024 (f-gate)   [u = 8b + w]
// Warp w (w>=8): rows rA=u+2048 (g-gate), rB=u+3072 (o-gate)   [u = 8b + w-8]
// Producer path: pair (w, w+8) syncs via named barrier (64 threads); warp w
// lane0 computes the cell and publishes the tagged h — no full-CTA wait.
// Exchange: R4-proven per-thread poll (thread polls its own 2 tagged words).
// sh is double-buffered: dot reads sh[t&1], pollers write sh[(t+1)&1];
// ONE full __syncthreads per step.
__global__ void __launch_bounds__(512, 1) lstm_kernel(const float* __restrict__ Ww)
{
    const int tid  = threadIdx.x;
    const int w    = tid >> 5;
    const int lane = tid & 31;
    const int d    = w & 7;
    const int u    = blockIdx.x * 8 + d;
    const int rA   = (w < 8) ? u : (u + 2048);
    const int rB   = rA + 1024;

    __shared__ float  sh[2][HID];   // double-buffered h stage
    __shared__ float2 gq2[8];       // (g, o) handoff from warp d+8 to warp d

    // recurrent weights (columns 1024..2047 of Ww) in registers, float4-packed
    float2 wa[16], wb[16];
    {
        const float4* WA = (const float4*)(Ww + (size_t)rA * (INW + HID) + INW);
        const float4* WB = (const float4*)(Ww + (size_t)rB * (INW + HID) + INW);
#pragma unroll
        for (int j = 0; j < 8; j++) {
            float4 a = WA[lane + 32 * j];
            float4 b = WB[lane + 32 * j];
            wa[2 * j]     = make_float2(a.x, a.y);
            wa[2 * j + 1] = make_float2(a.z, a.w);
            wb[2 * j]     = make_float2(b.x, b.y);
            wb[2 * j + 1] = make_float2(b.z, b.w);
        }
    }

    // h_{-1} = 0 into buffer 0
    ((float2*)sh[0])[tid] = make_float2(0.0f, 0.0f);

    // pre[0] for this warp's 2 rows (lane 0 only)
    float preA = 0.0f, preB = 0.0f;
    if (lane == 0) {
        preA = g_pre[rA];
        preB = g_pre[rB];
    }

    float c_state = 0.0f;   // live in lane 0 of warps 0..7 (one unit each)
    __syncthreads();

    for (int t = 0; t < T_STEPS; t++) {
        // ---- dot products over h_{t-1} in sh[t&1] (LDS.128, conflict-free) ----
        float2 aA = make_float2(0.0f, 0.0f);
        float2 aB = make_float2(0.0f, 0.0f);
        const float4* hp4 = (const float4*)sh[t & 1];
#pragma unroll
        for (int j = 0; j < 8; j++) {
            float4 h4 = hp4[lane + 32 * j];
            float2 h01 = make_float2(h4.x, h4.y);
            float2 h23 = make_float2(h4.z, h4.w);
            aA = ffma2(wa[2 * j],     h01, aA);
            aA = ffma2(wa[2 * j + 1], h23, aA);
            aB = ffma2(wb[2 * j],     h01, aB);
            aB = ffma2(wb[2 * j + 1], h23, aB);
        }
        float sA = aA.x + aA.y;
        float sB = aB.x + aB.y;
#pragma unroll
        for (int off = 16; off > 0; off >>= 1) {
            sA += __shfl_down_sync(0xffffffffu, sA, off);
            sB += __shfl_down_sync(0xffffffffu, sB, off);
        }

        // ---- pairwise producer path: unit d handled by warps d and d+8 ----
        if (w >= 8) {
            if (lane == 0) gq2[d] = make_float2(sA + preA, sB + preB);  // (g, o)
            bar_pair(1 + d);
        } else {
            bar_pair(1 + d);
            if (lane == 0) {
                float2 go = gq2[d];
                float ig = fsig(sA + preA);
                float fg = fsig(sB + preB);
                float gg = ftanh_acc(go.x);
                float og = fsig(go.y);
                c_state  = fg * c_state + ig * gg;
                float h  = og * ftanh_acc(c_state);
                unsigned long long word =
                    ((unsigned long long)(t + 1) << 32) |
                    (unsigned long long)__float_as_uint(h);
                st_tag_u64(&g_htag[t & 1][u], word);
                g_hall[(size_t)t * HID + u] = h;
            }
        }

        if (t + 1 < T_STEPS) {
            // prefetch pre[t+1] (overlaps the poll)
            if (lane == 0) {
                preA = g_pre[(size_t)(t + 1) * G4 + rA];
                preB = g_pre[(size_t)(t + 1) * G4 + rB];
            }

            // ---- per-thread poll: own 2 tagged words (R4-proven) ----
            const unsigned long long* src = &g_htag[t & 1][2 * tid];
            const unsigned long long want = (unsigned long long)(t + 1);
            ulonglong2 v;
            for (;;) {
                v = ld_tag_v2(src);
                if ((v.x >> 32) == want && (v.y >> 32) == want) break;
            }
            ((float2*)sh[(t + 1) & 1])[tid] = make_float2(
                __uint_as_float((unsigned)(v.x & 0xffffffffu)),
                __uint_as_float((unsigned)(v.y & 0xffffffffu)));
            __syncthreads();     // the single full barrier per step
        }
    }
}

// ---------------- launch -------------------------------------------------------
extern "C" void kernel_launch(void* const* d_in, const int* in_sizes, int n_in,
                              void* d_out, int out_size)
{
    const float* x   = (const float*)d_in[0];  // [8192, 1, 1024]
    const float* Ww  = (const float*)d_in[1];  // [4096, 2048]
    const float* Wb  = (const float*)d_in[2];  // [4096]
    const float* ow  = (const float*)d_in[3];  // [1024, 1024]
    const float* ob  = (const float*)d_in[4];  // [1024]
    float*       out = (float*)d_out;          // [8192, 1, 1024]

    init_tags_kernel<<<(2 * HID + 255) / 256, 256>>>();

    dim3 gridA(G4 / 128, T_STEPS / 128);       // 32 x 64
    gemm_pre_kernel<<<gridA, 256>>>(x, Ww, Wb);

    lstm_kernel<<<NCTA, 512>>>(Ww);

    dim3 gridC(HID / 128, T_STEPS / 128);      // 8 x 64
    gemm_out_kernel<<<gridC, 256>>>(ow, ob, out);
}

// round 12
// speedup vs baseline: 3.0105x; 3.0105x over previous
#include <cuda_runtime.h>
#include <cuda_bf16.h>
#include <string.h>
#include <cooperative_groups.h>
#include <cooperative_groups/reduce.h>

namespace cg = cooperative_groups;

#define T_STEPS 8192
#define HID     1024
#define G4      4096   // 4*HID
#define INW     1024
#define NCTA    128

// ---------------- static device scratch (no runtime allocation) --------------
__device__ float g_pre[(size_t)T_STEPS * G4];    // 128 MB: x-projection of gates
__device__ float g_hall[(size_t)T_STEPS * HID];  // 32 MB: all hidden states
// tagged h ring: element = (tag:32 << 32) | float_bits(h).  slot = t&1, tag = t+1
__device__ __align__(32) unsigned long long g_htag[2][HID];

// ---------------- small PTX helpers ------------------------------------------
__device__ __forceinline__ ulonglong2 ld_tag_v2(const unsigned long long* p) {
    ulonglong2 v;
    asm volatile("ld.relaxed.gpu.global.v2.u64 {%0,%1}, [%2];"
                 : "=l"(v.x), "=l"(v.y) : "l"(p) : "memory");
    return v;
}
__device__ __forceinline__ void st_tag_u64(unsigned long long* p, unsigned long long v) {
    asm volatile("st.relaxed.gpu.global.u64 [%0], %1;" :: "l"(p), "l"(v) : "memory");
}
__device__ __forceinline__ float2 ffma2(float2 a, float2 b, float2 c) {
    unsigned long long A, B, C, D;
    memcpy(&A, &a, 8); memcpy(&B, &b, 8); memcpy(&C, &c, 8);
    asm("fma.rn.f32x2 %0, %1, %2, %3;" : "=l"(D) : "l"(A), "l"(B), "l"(C));
    float2 d; memcpy(&d, &D, 8); return d;
}
__device__ __forceinline__ float2 fpack2(float a) {
    float2 r;
    unsigned long long R;
    asm("mov.b64 %0, {%1, %1};" : "=l"(R) : "f"(a));
    memcpy(&r, &R, 8); return r;
}
__device__ __forceinline__ float fsig(float x) {
    return __fdividef(1.0f, 1.0f + __expf(-x));
}
__device__ __forceinline__ float ftanh_acc(float x) {
    float xc = fminf(fmaxf(x, -15.0f), 15.0f);
    float e  = __expf(2.0f * xc);
    return __fdividef(e - 1.0f, e + 1.0f);
}

// ---------------- init: zero the tagged ring ----------------------------------
__global__ void init_tags_kernel() {
    int i = blockIdx.x * blockDim.x + threadIdx.x;
    if (i < 2 * HID) ((unsigned long long*)g_htag)[i] = 0ull;
}

// ---------------- fp32 NT GEMM: C = A*B^T + bias (reg-staged pipeline) --------
// A: [M x K] row-major (lda), B: [N x K] row-major (ldb), C: [M x N] (ldc)
// BM=BN=128, BK=16, 256 threads, 8x8 microtile (as 8x4 float2).
__device__ __forceinline__ void gemm_body(
    const float* __restrict__ A, int lda,
    const float* __restrict__ B, int ldb,
    const float* __restrict__ bias,
    float* __restrict__ C, int ldc, int K)
{
    __shared__ float As[16][132];
    __shared__ float Bs[16][132];

    const int tid  = threadIdx.x;
    const int tx   = tid & 15;          // N-dir microtile
    const int ty   = tid >> 4;          // M-dir microtile
    const int brow = blockIdx.y * 128;
    const int bcol = blockIdx.x * 128;
    const int lr   = tid >> 2;          // 0..63 (load row)
    const int lc   = (tid & 3) << 2;    // 0,4,8,12 (load col group)

    float2 acc[8][4];
#pragma unroll
    for (int i = 0; i < 8; i++)
#pragma unroll
        for (int j = 0; j < 4; j++) acc[i][j] = make_float2(0.0f, 0.0f);

    const float* Aptr = A + (size_t)(brow + lr) * lda + lc;
    const float* Bptr = B + (size_t)(bcol + lr) * ldb + lc;

    float4 va[2], vb[2];
#pragma unroll
    for (int r = 0; r < 2; r++) {
        va[r] = *(const float4*)(Aptr + (size_t)(64 * r) * lda);
        vb[r] = *(const float4*)(Bptr + (size_t)(64 * r) * ldb);
    }

    const int NT = K / 16;
    for (int tile = 0; tile < NT; ++tile) {
#pragma unroll
        for (int r = 0; r < 2; r++) {
            As[lc + 0][lr + 64 * r] = va[r].x;
            As[lc + 1][lr + 64 * r] = va[r].y;
            As[lc + 2][lr + 64 * r] = va[r].z;
            As[lc + 3][lr + 64 * r] = va[r].w;
            Bs[lc + 0][lr + 64 * r] = vb[r].x;
            Bs[lc + 1][lr + 64 * r] = vb[r].y;
            Bs[lc + 2][lr + 64 * r] = vb[r].z;
            Bs[lc + 3][lr + 64 * r] = vb[r].w;
        }
        __syncthreads();

        if (tile + 1 < NT) {
            const int k0 = (tile + 1) * 16;
#pragma unroll
            for (int r = 0; r < 2; r++) {
                va[r] = *(const float4*)(Aptr + (size_t)(64 * r) * lda + k0);
                vb[r] = *(const float4*)(Bptr + (size_t)(64 * r) * ldb + k0);
            }
        }

#pragma unroll
        for (int kk = 0; kk < 16; kk++) {
            float  ra[8];
            float2 rb[4];
            *(float4*)(ra)     = *(const float4*)&As[kk][ty * 8];
            *(float4*)(ra + 4) = *(const float4*)&As[kk][ty * 8 + 4];
            *(float4*)(&rb[0]) = *(const float4*)&Bs[kk][tx * 8];
            *(float4*)(&rb[2]) = *(const float4*)&Bs[kk][tx * 8 + 4];
#pragma unroll
            for (int i = 0; i < 8; i++) {
                float2 a2 = fpack2(ra[i]);
#pragma unroll
                for (int j = 0; j < 4; j++)
                    acc[i][j] = ffma2(a2, rb[j], acc[i][j]);
            }
        }
        __syncthreads();
    }

    float2 bv[4];
    *(float4*)(&bv[0]) = *(const float4*)&bias[bcol + tx * 8];
    *(float4*)(&bv[2]) = *(const float4*)&bias[bcol + tx * 8 + 4];
#pragma unroll
    for (int i = 0; i < 8; i++) {
        float4 o0, o1;
        o0.x = acc[i][0].x + bv[0].x; o0.y = acc[i][0].y + bv[0].y;
        o0.z = acc[i][1].x + bv[1].x; o0.w = acc[i][1].y + bv[1].y;
        o1.x = acc[i][2].x + bv[2].x; o1.y = acc[i][2].y + bv[2].y;
        o1.z = acc[i][3].x + bv[3].x; o1.w = acc[i][3].y + bv[3].y;
        float* crow = C + (size_t)(brow + ty * 8 + i) * ldc + bcol + tx * 8;
        *(float4*)(crow)     = o0;
        *(float4*)(crow + 4) = o1;
    }
}

__global__ void __launch_bounds__(256, 2) gemm_pre_kernel(
    const float* __restrict__ x, const float* __restrict__ Ww,
    const float* __restrict__ Wb)
{
    gemm_body(x, INW, Ww, INW + HID, Wb, g_pre, G4, INW);
}

__global__ void __launch_bounds__(256, 2) gemm_out_kernel(
    const float* __restrict__ ow, const float* __restrict__ ob,
    float* __restrict__ out)
{
    gemm_body(g_hall, HID, ow, HID, ob, out, HID, HID);
}

// ---------------- persistent LSTM recurrence (R4 structure, frozen) -----------
// 128 CTAs x 512 threads (16 warps). CTA owns units [8b, 8b+8).
// Warp w (w<8):  rows rA=u0+w (i-gate), rB=rA+1024 (f-gate)
// Warp w (w>=8): rows rA=u0+(w-8)+2048 (g-gate), rB=rA+1024 (o-gate)
// Exchange: per-thread fused tag+data poll of own 2 words (R4-proven).
// ONLY change vs R4: warp reduce via cg::reduce -> REDUX.SUM.F32 on sm_103a
// (2 instructions/warp instead of 10 SHFLs; chain ~130 -> ~40 cyc).
__global__ void __launch_bounds__(512, 1) lstm_kernel(const float* __restrict__ Ww)
{
    const int tid  = threadIdx.x;
    const int w    = tid >> 5;
    const int lane = tid & 31;
    const int d    = w & 7;
    const int u    = blockIdx.x * 8 + d;
    const int rA   = (w < 8) ? u : (u + 2048);
    const int rB   = rA + 1024;

    auto warp32 = cg::tiled_partition<32>(cg::this_thread_block());

    __shared__ float  sh[HID];   // h_{t-1} stage (single buffer: reads complete
                                 // before barrier #1; poll writes after it)
    __shared__ float4 gq[8];     // (i, f, g, o) per unit

    // recurrent weights (columns 1024..2047 of Ww) in registers
    float2 wa[16], wb[16];
    {
        const float2* WA = (const float2*)(Ww + (size_t)rA * (INW + HID) + INW);
        const float2* WB = (const float2*)(Ww + (size_t)rB * (INW + HID) + INW);
#pragma unroll
        for (int i = 0; i < 16; i++) {
            wa[i] = WA[lane + 32 * i];
            wb[i] = WB[lane + 32 * i];
        }
    }

    // h_{-1} = 0
    ((float2*)sh)[tid] = make_float2(0.0f, 0.0f);

    // pre[0] for this warp's 2 rows (lane 0 only)
    float preA = 0.0f, preB = 0.0f;
    if (lane == 0) {
        preA = g_pre[rA];
        preB = g_pre[rB];
    }

    float c_state = 0.0f;   // live only in threads 0..7
    __syncthreads();

    for (int t = 0; t < T_STEPS; t++) {
        // ---- dot products over h_{t-1} in sh ----
        float2 aA = make_float2(0.0f, 0.0f);
        float2 aB = make_float2(0.0f, 0.0f);
        const float2* hp = (const float2*)sh;
#pragma unroll
        for (int i = 0; i < 16; i++) {
            float2 h2 = hp[lane + 32 * i];
            aA = ffma2(wa[i], h2, aA);
            aB = ffma2(wb[i], h2, aB);
        }
        // warp reduce: REDUX.SUM.F32 on sm_103a via cooperative_groups
        float sA = cg::reduce(warp32, aA.x + aA.y, cg::plus<float>());
        float sB = cg::reduce(warp32, aB.x + aB.y, cg::plus<float>());

        if (lane == 0) {
            if (w < 8) { gq[d].x = sA + preA; gq[d].y = sB + preB; }
            else       { gq[d].z = sA + preA; gq[d].w = sB + preB; }
        }
        __syncthreads();                               // barrier #1

        // ---- cell update (8 threads, all in warp 0) + tagged store ----
        if (tid < 8) {
            float4 G = gq[tid];
            float ig = fsig(G.x);
            float fg = fsig(G.y);
            float gg = ftanh_acc(G.z);
            float og = fsig(G.w);
            c_state = fg * c_state + ig * gg;
            float h = og * ftanh_acc(c_state);
            int uu = blockIdx.x * 8 + tid;
            unsigned long long word =
                ((unsigned long long)(t + 1) << 32) |
                (unsigned long long)__float_as_uint(h);
            st_tag_u64(&g_htag[t & 1][uu], word);
            g_hall[(size_t)t * HID + uu] = h;
        }

        if (t + 1 < T_STEPS) {
            // prefetch pre[t+1] (overlaps the poll)
            if (lane == 0) {
                preA = g_pre[(size_t)(t + 1) * G4 + rA];
                preB = g_pre[(size_t)(t + 1) * G4 + rB];
            }

            // ---- per-thread poll: own 2 tagged words (R4-proven) ----
            const unsigned long long* src = &g_htag[t & 1][2 * tid];
            const unsigned long long want = (unsigned long long)(t + 1);
            ulonglong2 v;
            for (;;) {
                v = ld_tag_v2(src);
                if ((v.x >> 32) == want && (v.y >> 32) == want) break;
            }
            ((float2*)sh)[tid] = make_float2(
                __uint_as_float((unsigned)(v.x & 0xffffffffu)),
                __uint_as_float((unsigned)(v.y & 0xffffffffu)));
            __syncthreads();                           // barrier #2
        }
    }
}

// ---------------- launch -------------------------------------------------------
extern "C" void kernel_launch(void* const* d_in, const int* in_sizes, int n_in,
                              void* d_out, int out_size)
{
    const float* x   = (const float*)d_in[0];  // [8192, 1, 1024]
    const float* Ww  = (const float*)d_in[1];  // [4096, 2048]
    const float* Wb  = (const float*)d_in[2];  // [4096]
    const float* ow  = (const float*)d_in[3];  // [1024, 1024]
    const float* ob  = (const float*)d_in[4];  // [1024]
    float*       out = (float*)d_out;          // [8192, 1, 1024]

    init_tags_kernel<<<(2 * HID + 255) / 256, 256>>>();

    dim3 gridA(G4 / 128, T_STEPS / 128);       // 32 x 64
    gemm_pre_kernel<<<gridA, 256>>>(x, Ww, Wb);

    lstm_kernel<<<NCTA, 512>>>(Ww);

    dim3 gridC(HID / 128, T_STEPS / 128);      // 8 x 64
    gemm_out_kernel<<<gridC, 256>>>(ow, ob, out);
}